// round 12
// baseline (speedup 1.0000x reference)
#include <cuda_runtime.h>
#include <cuda_fp16.h>
#include <cstdint>
#include <math.h>

// ---------------------------------------------------------------------------
// 8-expert FFN, fp32: per expert [2048x2048]@[2048x8192] -> GELU -> @[8192x2048]
// compute_103 portable path. R12: fp16 mma.m16n8k16 kernel at 3 CTAs/SM
// (128 thr, 2 stages, 64KB smem, single-buffered fragments, <=170 regs) so
// every SMSP holds 3 independent warps to cover per-CTA barrier bubbles.
// ---------------------------------------------------------------------------
#define EXP_E 8
#define EXP_C 2048
#define EXP_D 2048
#define EXP_F 8192

__device__ __align__(256) __half g_H  [(size_t)EXP_E * EXP_C * EXP_F];  // gelu(X@W1+b1)
__device__ __align__(256) __half g_Xh [(size_t)EXP_E * EXP_C * EXP_D];  // half X
__device__ __align__(256) __half g_W1h[(size_t)EXP_E * EXP_D * EXP_F];  // [E][D/64][F][64]
__device__ __align__(256) __half g_W2h[(size_t)EXP_E * EXP_F * EXP_D];  // [E][F/64][D][64]

#define BM 128
#define BN 128
#define BK 64
#define STAGES 2
#define ROW_BYTES 128                       // 64 halves per k-row
#define A_BYTES (BM * ROW_BYTES)            // 16384
#define B_BYTES (BN * ROW_BYTES)            // 16384
#define STAGE_BYTES (A_BYTES + B_BYTES)     // 32768
#define SMEM_BYTES (STAGES * STAGE_BYTES)   // 65536/CTA; 3 CTAs = 192KB/SM

// ---------------------------------------------------------------------------
// Helpers
// ---------------------------------------------------------------------------
__device__ __forceinline__ uint32_t smem_u32(const void* p) {
    uint32_t a;
    asm("{ .reg .u64 t; cvta.to.shared.u64 t, %1; cvt.u32.u64 %0, t; }"
        : "=r"(a) : "l"(p));
    return a;
}

#define CP_ASYNC_CG(dst_u32, src_ptr) \
    asm volatile("cp.async.cg.shared.global [%0], [%1], 16;" \
                 :: "r"(dst_u32), "l"(src_ptr) : "memory")
#define CP_ASYNC_COMMIT() asm volatile("cp.async.commit_group;" ::: "memory")
#define CP_ASYNC_WAIT(n)  asm volatile("cp.async.wait_group %0;" :: "n"(n) : "memory")

#define LDSM_X4(r, addr) \
    asm volatile("ldmatrix.sync.aligned.m8n8.x4.shared.b16 {%0,%1,%2,%3}, [%4];" \
                 : "=r"((r)[0]), "=r"((r)[1]), "=r"((r)[2]), "=r"((r)[3]) \
                 : "r"(addr))

// fp16 MMA, fp32 accumulate
__device__ __forceinline__ void mma_f16(float* d, const uint32_t* a,
                                        uint32_t b0, uint32_t b1) {
    asm volatile(
        "mma.sync.aligned.m16n8k16.row.col.f32.f16.f16.f32 "
        "{%0,%1,%2,%3}, {%4,%5,%6,%7}, {%8,%9}, {%0,%1,%2,%3};"
        : "+f"(d[0]), "+f"(d[1]), "+f"(d[2]), "+f"(d[3])
        : "r"(a[0]), "r"(a[1]), "r"(a[2]), "r"(a[3]), "r"(b0), "r"(b1));
}

__device__ __forceinline__ float gelu_tanh(float x) {
    float u = 0.7978845608028654f * fmaf(0.044715f * x, x * x, x);
    return 0.5f * x * (1.0f + tanhf(u));
}

// Convert X: fp32 -> fp16 (RNE).
__global__ void __launch_bounds__(256)
to_half_pass(const float4* __restrict__ in, uint2* __restrict__ out, size_t n4) {
    size_t i = (size_t)blockIdx.x * blockDim.x + threadIdx.x;
    size_t stride = (size_t)gridDim.x * blockDim.x;
    for (; i < n4; i += stride) {
        float4 v = in[i];
        __half2 h0 = __floats2half2_rn(v.x, v.y);
        __half2 h1 = __floats2half2_rn(v.z, v.w);
        uint2 u;
        u.x = *reinterpret_cast<uint32_t*>(&h0);
        u.y = *reinterpret_cast<uint32_t*>(&h1);
        out[i] = u;
    }
}

// Transpose-pack weights to half, 64-wide: W[e][k][n] -> Wt[e][k/64][n][64].
__global__ void __launch_bounds__(256)
transpose_pack64_h(const float* __restrict__ W, __half* __restrict__ Wt,
                   int K, int N) {
    const int n  = blockIdx.x * 256 + threadIdx.x;
    const int kt = blockIdx.y;
    const int e  = blockIdx.z;
    const float* src = W + ((size_t)e * K + (size_t)kt * 64) * N + n;
    __half* dst = Wt + (((size_t)e * (K / 64) + kt) * N + n) * 64;
#pragma unroll
    for (int j = 0; j < 64; j += 8) {
        uint4 u;
        __half2 h;
        h = __floats2half2_rn(src[(size_t)(j+0)*N], src[(size_t)(j+1)*N]);
        u.x = *reinterpret_cast<uint32_t*>(&h);
        h = __floats2half2_rn(src[(size_t)(j+2)*N], src[(size_t)(j+3)*N]);
        u.y = *reinterpret_cast<uint32_t*>(&h);
        h = __floats2half2_rn(src[(size_t)(j+4)*N], src[(size_t)(j+5)*N]);
        u.z = *reinterpret_cast<uint32_t*>(&h);
        h = __floats2half2_rn(src[(size_t)(j+6)*N], src[(size_t)(j+7)*N]);
        u.w = *reinterpret_cast<uint32_t*>(&h);
        *reinterpret_cast<uint4*>(dst + j) = u;
    }
}

// ---------------------------------------------------------------------------
// Batched GEMM: Out[e][m][n] = epi( sum_k A[e][m][k]*B[e][k][n] + bias[e][n] )
//   A:  [E][2048][K] row-major half
//   Bt: [E][K/64][ldN][64] K-major packed half
//   CTA 128x128x64, 128 threads (warp grid 2x2 of 64x64), 3 CTAs/SM.
// ---------------------------------------------------------------------------
template <bool GELU, typename OutT>
__global__ void __launch_bounds__(128, 3)
moe_gemm_f16(const __half* __restrict__ A, const __half* __restrict__ Bt,
             const float* __restrict__ bias, OutT* __restrict__ Out,
             int K, int ldN)
{
    extern __shared__ char smem[];
    const int tid  = threadIdx.x;
    const int warp = tid >> 5;
    const int lane = tid & 31;
    const int e  = blockIdx.z;
    const int m0 = blockIdx.x * BM;
    const int n0 = blockIdx.y * BN;
    const int KT = K / BK;

    const __half* Ae  = A  + (size_t)e * EXP_C * K;
    const __half* Bte = Bt + (size_t)e * (K / 64) * ldN * 64 + (size_t)n0 * 64;
    const float*  be  = bias + (size_t)e * ldN;
    OutT*         Oe  = Out  + (size_t)e * EXP_C * ldN;

    const uint32_t sbase = smem_u32(smem);

    const int wm = warp >> 1;    // warp grid 2(M) x 2(N), warp tile 64x64
    const int wn = warp & 1;

    // ---- cp.async geometry: row = tid>>3 (+16*rep), chunk = tid&7 ----
    const int crow   = tid >> 3;              // 0..15
    const int cchunk = tid & 7;               // 8 x 16B per 128B row
    const int cswz   = crow & 7;
    const uint32_t a_dst0 = (uint32_t)(crow * ROW_BYTES + ((cchunk ^ cswz) * 16));

    // running gmem pointers (halves)
    const __half* a_run = Ae  + (size_t)(m0 + crow) * K + cchunk * 8;
    const __half* b_run = Bte + (size_t)crow * 64 + cchunk * 8;

    // ---- ldmatrix geometry (kk-step address = base ^ (kk*32)) ----
    const int alrow = (lane & 7) + ((lane >> 3) & 1) * 8;
    const int ahi   = lane >> 4;
    const int blrow = (lane & 7) + ((lane >> 4) & 1) * 8;
    const int bhi   = (lane >> 3) & 1;
    uint32_t afrag[4], bfrag[4];
#pragma unroll
    for (int i = 0; i < 4; ++i) {
        int ra = wm * 64 + i * 16 + alrow;
        afrag[i] = (uint32_t)(ra * ROW_BYTES + ((ahi ^ (ra & 7)) * 16));
        int rb = wn * 64 + i * 16 + blrow;
        bfrag[i] = (uint32_t)(A_BYTES + rb * ROW_BYTES + ((bhi ^ (rb & 7)) * 16));
    }

    float acc[4][8][4];
#pragma unroll
    for (int mt = 0; mt < 4; ++mt)
#pragma unroll
        for (int nt = 0; nt < 8; ++nt)
#pragma unroll
            for (int j = 0; j < 4; ++j) acc[mt][nt][j] = 0.0f;

    auto issue_tile = [&](int stg) {
        const uint32_t st = sbase + (uint32_t)stg * STAGE_BYTES;
#pragma unroll
        for (int rep = 0; rep < 8; ++rep)
            CP_ASYNC_CG(st + a_dst0 + rep * 16u * ROW_BYTES,
                        a_run + (size_t)rep * 16 * K);
#pragma unroll
        for (int rep = 0; rep < 8; ++rep)
            CP_ASYNC_CG(st + A_BYTES + a_dst0 + rep * 16u * ROW_BYTES,
                        b_run + rep * 16 * 64);
        a_run += BK;
        b_run += (size_t)ldN * 64;
    };

    // prologue: fill stage 0
    issue_tile(0);
    CP_ASYNC_COMMIT();

    int s = 0;   // consume stage; fill stage = s^1
    for (int t = 0; t < KT; ++t) {
        CP_ASYNC_WAIT(0);          // tile t resident
        __syncthreads();
        if (t + 1 < KT) issue_tile(s ^ 1);
        CP_ASYNC_COMMIT();

        const uint32_t sA = sbase + (uint32_t)s * STAGE_BYTES;
        s ^= 1;

        // 4 k16-steps, single-buffered fragments (3 warps/SMSP cover gaps)
#pragma unroll
        for (int kk = 0; kk < 4; ++kk) {
            const uint32_t x = (uint32_t)kk * 32u;
            uint32_t af[4][4], bf[4][4];
#pragma unroll
            for (int i = 0; i < 4; ++i) LDSM_X4(af[i], sA + (afrag[i] ^ x));
#pragma unroll
            for (int i = 0; i < 4; ++i) LDSM_X4(bf[i], sA + (bfrag[i] ^ x));
#pragma unroll
            for (int mt = 0; mt < 4; ++mt)
#pragma unroll
                for (int nt = 0; nt < 8; ++nt)
                    mma_f16(acc[mt][nt], af[mt],
                            bf[nt >> 1][(nt & 1) * 2],
                            bf[nt >> 1][(nt & 1) * 2 + 1]);
        }
    }

    // ---- epilogue: direct reg -> gmem, fused bias (+GELU) ----
    const int g     = lane >> 2;
    const int cpair = (lane & 3) * 2;
#pragma unroll
    for (int mt = 0; mt < 4; ++mt) {
#pragma unroll
        for (int h = 0; h < 2; ++h) {
            const int grow = m0 + wm * 64 + mt * 16 + g + h * 8;
            OutT* op = Oe + (size_t)grow * ldN + n0 + wn * 64 + cpair;
#pragma unroll
            for (int nt = 0; nt < 8; ++nt) {
                const float2 bv = *reinterpret_cast<const float2*>(
                    be + n0 + wn * 64 + nt * 8 + cpair);
                float x0 = acc[mt][nt][h * 2]     + bv.x;
                float x1 = acc[mt][nt][h * 2 + 1] + bv.y;
                if (GELU) {
                    __half2 hv = __floats2half2_rn(gelu_tanh(x0), gelu_tanh(x1));
                    *reinterpret_cast<__half2*>((__half*)op + nt * 8) = hv;
                } else {
                    *reinterpret_cast<float2*>((float*)op + nt * 8) =
                        make_float2(x0, x1);
                }
            }
        }
    }
}

// ---------------------------------------------------------------------------
// kernel_launch
// ---------------------------------------------------------------------------
extern "C" void kernel_launch(void* const* d_in, const int* in_sizes, int n_in,
                              void* d_out, int out_size) {
    (void)in_sizes; (void)n_in; (void)out_size;
    const float* inputs = (const float*)d_in[0];
    const float* w1     = (const float*)d_in[1];
    const float* b1     = (const float*)d_in[2];
    const float* w2     = (const float*)d_in[3];
    const float* b2     = (const float*)d_in[4];
    float* out = (float*)d_out;

    void *hp, *xp, *w1p, *w2p;
    cudaGetSymbolAddress(&hp,  g_H);
    cudaGetSymbolAddress(&xp,  g_Xh);
    cudaGetSymbolAddress(&w1p, g_W1h);
    cudaGetSymbolAddress(&w2p, g_W2h);
    __half* H   = (__half*)hp;
    __half* Xh  = (__half*)xp;
    __half* W1h = (__half*)w1p;
    __half* W2h = (__half*)w2p;

    const size_t nX = (size_t)EXP_E * EXP_C * EXP_D / 4;
    to_half_pass<<<2048, 256>>>((const float4*)inputs, (uint2*)Xh, nX);

    dim3 t1(EXP_F / 256, EXP_D / 64, EXP_E);   // W1: K=D, N=F
    transpose_pack64_h<<<t1, 256>>>(w1, W1h, EXP_D, EXP_F);
    dim3 t2(EXP_D / 256, EXP_F / 64, EXP_E);   // W2: K=F, N=D
    transpose_pack64_h<<<t2, 256>>>(w2, W2h, EXP_F, EXP_D);

    cudaFuncSetAttribute((const void*)moe_gemm_f16<true, __half>,
                         cudaFuncAttributeMaxDynamicSharedMemorySize, SMEM_BYTES);
    cudaFuncSetAttribute((const void*)moe_gemm_f16<false, float>,
                         cudaFuncAttributeMaxDynamicSharedMemorySize, SMEM_BYTES);

    dim3 g1(EXP_C / BM, EXP_F / BN, EXP_E);    // (16, 64, 8)
    moe_gemm_f16<true, __half><<<g1, 128, SMEM_BYTES>>>(Xh, W1h, b1, H, EXP_D, EXP_F);

    dim3 g2(EXP_C / BM, EXP_D / BN, EXP_E);    // (16, 16, 8)
    moe_gemm_f16<false, float><<<g2, 128, SMEM_BYTES>>>(H, W2h, b2, out, EXP_F, EXP_D);
}

// round 13
// speedup vs baseline: 1.1673x; 1.1673x over previous
#include <cuda_runtime.h>
#include <cuda_fp16.h>
#include <cstdint>
#include <math.h>

// ---------------------------------------------------------------------------
// 8-expert FFN, fp32: per expert [2048x2048]@[2048x8192] -> GELU -> @[8192x2048]
// compute_103 portable path. R13: R11 core (fp16 mma.m16n8k16, BK=64, 3
// stages, 2 CTAs/SM, dbl-buffered frags) restructured into a CUTLASS-style
// cross-tile pipeline: the per-tile wait+syncthreads+LDSM chain is issued
// BEFORE the last kk's MMA burst, hiding it under ~32 MMAs.
// ---------------------------------------------------------------------------
#define EXP_E 8
#define EXP_C 2048
#define EXP_D 2048
#define EXP_F 8192

__device__ __align__(256) __half g_H  [(size_t)EXP_E * EXP_C * EXP_F];  // gelu(X@W1+b1)
__device__ __align__(256) __half g_Xh [(size_t)EXP_E * EXP_C * EXP_D];  // half X
__device__ __align__(256) __half g_W1h[(size_t)EXP_E * EXP_D * EXP_F];  // [E][D/64][F][64]
__device__ __align__(256) __half g_W2h[(size_t)EXP_E * EXP_F * EXP_D];  // [E][F/64][D][64]

#define BM 128
#define BN 128
#define BK 64
#define STAGES 3
#define ROW_BYTES 128                       // 64 halves per k-row
#define A_BYTES (BM * ROW_BYTES)            // 16384
#define B_BYTES (BN * ROW_BYTES)            // 16384
#define STAGE_BYTES (A_BYTES + B_BYTES)     // 32768
#define SMEM_BYTES (STAGES * STAGE_BYTES)   // 98304/CTA; 2 CTAs = 192KB/SM

// ---------------------------------------------------------------------------
// Helpers
// ---------------------------------------------------------------------------
__device__ __forceinline__ uint32_t smem_u32(const void* p) {
    uint32_t a;
    asm("{ .reg .u64 t; cvta.to.shared.u64 t, %1; cvt.u32.u64 %0, t; }"
        : "=r"(a) : "l"(p));
    return a;
}

#define CP_ASYNC_CG(dst_u32, src_ptr) \
    asm volatile("cp.async.cg.shared.global [%0], [%1], 16;" \
                 :: "r"(dst_u32), "l"(src_ptr) : "memory")
#define CP_ASYNC_COMMIT() asm volatile("cp.async.commit_group;" ::: "memory")
#define CP_ASYNC_WAIT(n)  asm volatile("cp.async.wait_group %0;" :: "n"(n) : "memory")

#define LDSM_X4(r, addr) \
    asm volatile("ldmatrix.sync.aligned.m8n8.x4.shared.b16 {%0,%1,%2,%3}, [%4];" \
                 : "=r"((r)[0]), "=r"((r)[1]), "=r"((r)[2]), "=r"((r)[3]) \
                 : "r"(addr))

// fp16 MMA, fp32 accumulate
__device__ __forceinline__ void mma_f16(float* d, const uint32_t* a,
                                        uint32_t b0, uint32_t b1) {
    asm volatile(
        "mma.sync.aligned.m16n8k16.row.col.f32.f16.f16.f32 "
        "{%0,%1,%2,%3}, {%4,%5,%6,%7}, {%8,%9}, {%0,%1,%2,%3};"
        : "+f"(d[0]), "+f"(d[1]), "+f"(d[2]), "+f"(d[3])
        : "r"(a[0]), "r"(a[1]), "r"(a[2]), "r"(a[3]), "r"(b0), "r"(b1));
}

__device__ __forceinline__ float gelu_tanh(float x) {
    float u = 0.7978845608028654f * fmaf(0.044715f * x, x * x, x);
    return 0.5f * x * (1.0f + tanhf(u));
}

// Convert X: fp32 -> fp16 (RNE).
__global__ void __launch_bounds__(256)
to_half_pass(const float4* __restrict__ in, uint2* __restrict__ out, size_t n4) {
    size_t i = (size_t)blockIdx.x * blockDim.x + threadIdx.x;
    size_t stride = (size_t)gridDim.x * blockDim.x;
    for (; i < n4; i += stride) {
        float4 v = in[i];
        __half2 h0 = __floats2half2_rn(v.x, v.y);
        __half2 h1 = __floats2half2_rn(v.z, v.w);
        uint2 u;
        u.x = *reinterpret_cast<uint32_t*>(&h0);
        u.y = *reinterpret_cast<uint32_t*>(&h1);
        out[i] = u;
    }
}

// Transpose-pack weights to half, 64-wide: W[e][k][n] -> Wt[e][k/64][n][64].
__global__ void __launch_bounds__(256)
transpose_pack64_h(const float* __restrict__ W, __half* __restrict__ Wt,
                   int K, int N) {
    const int n  = blockIdx.x * 256 + threadIdx.x;
    const int kt = blockIdx.y;
    const int e  = blockIdx.z;
    const float* src = W + ((size_t)e * K + (size_t)kt * 64) * N + n;
    __half* dst = Wt + (((size_t)e * (K / 64) + kt) * N + n) * 64;
#pragma unroll
    for (int j = 0; j < 64; j += 8) {
        uint4 u;
        __half2 h;
        h = __floats2half2_rn(src[(size_t)(j+0)*N], src[(size_t)(j+1)*N]);
        u.x = *reinterpret_cast<uint32_t*>(&h);
        h = __floats2half2_rn(src[(size_t)(j+2)*N], src[(size_t)(j+3)*N]);
        u.y = *reinterpret_cast<uint32_t*>(&h);
        h = __floats2half2_rn(src[(size_t)(j+4)*N], src[(size_t)(j+5)*N]);
        u.z = *reinterpret_cast<uint32_t*>(&h);
        h = __floats2half2_rn(src[(size_t)(j+6)*N], src[(size_t)(j+7)*N]);
        u.w = *reinterpret_cast<uint32_t*>(&h);
        *reinterpret_cast<uint4*>(dst + j) = u;
    }
}

// ---------------------------------------------------------------------------
// Batched GEMM: Out[e][m][n] = epi( sum_k A[e][m][k]*B[e][k][n] + bias[e][n] )
//   A:  [E][2048][K] row-major half
//   Bt: [E][K/64][ldN][64] K-major packed half
//   CTA 128x128x64, 128 threads (warp grid 2x2 of 64x64), 2 CTAs/SM.
// ---------------------------------------------------------------------------
template <bool GELU, typename OutT>
__global__ void __launch_bounds__(128, 2)
moe_gemm_f16(const __half* __restrict__ A, const __half* __restrict__ Bt,
             const float* __restrict__ bias, OutT* __restrict__ Out,
             int K, int ldN)
{
    extern __shared__ char smem[];
    const int tid  = threadIdx.x;
    const int warp = tid >> 5;
    const int lane = tid & 31;
    const int e  = blockIdx.z;
    const int m0 = blockIdx.x * BM;
    const int n0 = blockIdx.y * BN;
    const int KT = K / BK;

    const __half* Ae  = A  + (size_t)e * EXP_C * K;
    const __half* Bte = Bt + (size_t)e * (K / 64) * ldN * 64 + (size_t)n0 * 64;
    const float*  be  = bias + (size_t)e * ldN;
    OutT*         Oe  = Out  + (size_t)e * EXP_C * ldN;

    const uint32_t sbase = smem_u32(smem);

    const int wm = warp >> 1;    // warp grid 2(M) x 2(N), warp tile 64x64
    const int wn = warp & 1;

    // ---- cp.async geometry ----
    const int crow   = tid >> 3;              // 0..15
    const int cchunk = tid & 7;               // 8 x 16B per 128B row
    const int cswz   = crow & 7;
    const uint32_t a_dst0 = (uint32_t)(crow * ROW_BYTES + ((cchunk ^ cswz) * 16));

    const __half* a_run = Ae  + (size_t)(m0 + crow) * K + cchunk * 8;
    const __half* b_run = Bte + (size_t)crow * 64 + cchunk * 8;

    // ---- ldmatrix geometry (kk-step address = base ^ (kk*32)) ----
    const int alrow = (lane & 7) + ((lane >> 3) & 1) * 8;
    const int ahi   = lane >> 4;
    const int blrow = (lane & 7) + ((lane >> 4) & 1) * 8;
    const int bhi   = (lane >> 3) & 1;
    uint32_t afrag[4], bfrag[4];
#pragma unroll
    for (int i = 0; i < 4; ++i) {
        int ra = wm * 64 + i * 16 + alrow;
        afrag[i] = (uint32_t)(ra * ROW_BYTES + ((ahi ^ (ra & 7)) * 16));
        int rb = wn * 64 + i * 16 + blrow;
        bfrag[i] = (uint32_t)(A_BYTES + rb * ROW_BYTES + ((bhi ^ (rb & 7)) * 16));
    }

    float acc[4][8][4];
#pragma unroll
    for (int mt = 0; mt < 4; ++mt)
#pragma unroll
        for (int nt = 0; nt < 8; ++nt)
#pragma unroll
            for (int j = 0; j < 4; ++j) acc[mt][nt][j] = 0.0f;

    auto issue_tile = [&](int stg) {
        const uint32_t st = sbase + (uint32_t)stg * STAGE_BYTES;
#pragma unroll
        for (int rep = 0; rep < 8; ++rep)
            CP_ASYNC_CG(st + a_dst0 + rep * 16u * ROW_BYTES,
                        a_run + (size_t)rep * 16 * K);
#pragma unroll
        for (int rep = 0; rep < 8; ++rep)
            CP_ASYNC_CG(st + A_BYTES + a_dst0 + rep * 16u * ROW_BYTES,
                        b_run + rep * 16 * 64);
        a_run += BK;
        b_run += (size_t)ldN * 64;
    };

    // prologue: fill ALL 3 stages (KT = 32 or 128 >= 3 always)
#pragma unroll
    for (int t = 0; t < STAGES; ++t) {
        issue_tile(t);
        CP_ASYNC_COMMIT();
    }
    CP_ASYNC_WAIT(2);          // tile 0 resident (oldest group retires first)
    __syncthreads();

    // preload tile 0 / kk 0 fragments
    uint32_t af[2][4][4], bf[2][4][4];
#pragma unroll
    for (int i = 0; i < 4; ++i) LDSM_X4(af[0][i], sbase + afrag[i]);
#pragma unroll
    for (int i = 0; i < 4; ++i) LDSM_X4(bf[0][i], sbase + bfrag[i]);

    int s_cur = 0;
    for (int t = 0; t < KT; ++t) {
        const uint32_t sA = sbase + (uint32_t)s_cur * STAGE_BYTES;
        const int s_nxt = (s_cur + 1 == STAGES) ? 0 : s_cur + 1;
        const uint32_t sN = sbase + (uint32_t)s_nxt * STAGE_BYTES;

#pragma unroll
        for (int kk = 0; kk < 4; ++kk) {
            const int cur = kk & 1, nxt = cur ^ 1;
            if (kk < 3) {
                // prefetch fragments for kk+1 (same stage)
                const uint32_t x = (uint32_t)(kk + 1) * 32u;
#pragma unroll
                for (int i = 0; i < 4; ++i) LDSM_X4(af[nxt][i], sA + (afrag[i] ^ x));
#pragma unroll
                for (int i = 0; i < 4; ++i) LDSM_X4(bf[nxt][i], sA + (bfrag[i] ^ x));
            } else {
                // cross-tile boundary, BEFORE kk3's MMA burst:
                // tile t+1 resident (<=2 newer groups pending), all warps done
                // reading stage s_cur, prefetch next tile kk0, refill stage.
                CP_ASYNC_WAIT(2);
                __syncthreads();
                if (t + 1 < KT) {
#pragma unroll
                    for (int i = 0; i < 4; ++i) LDSM_X4(af[nxt][i], sN + afrag[i]);
#pragma unroll
                    for (int i = 0; i < 4; ++i) LDSM_X4(bf[nxt][i], sN + bfrag[i]);
                }
                if (t + STAGES < KT) issue_tile(s_cur);   // tile t+3 -> freed stage
                CP_ASYNC_COMMIT();                        // uniform group count
            }
#pragma unroll
            for (int mt = 0; mt < 4; ++mt)
#pragma unroll
                for (int nt = 0; nt < 8; ++nt)
                    mma_f16(acc[mt][nt], af[cur][mt],
                            bf[cur][nt >> 1][(nt & 1) * 2],
                            bf[cur][nt >> 1][(nt & 1) * 2 + 1]);
        }
        s_cur = s_nxt;
    }

    // ---- epilogue: direct reg -> gmem, fused bias (+GELU) ----
    const int g     = lane >> 2;
    const int cpair = (lane & 3) * 2;
    float2 bv[8];
#pragma unroll
    for (int nt = 0; nt < 8; ++nt)
        bv[nt] = *reinterpret_cast<const float2*>(be + n0 + wn * 64 + nt * 8 + cpair);

#pragma unroll
    for (int mt = 0; mt < 4; ++mt) {
#pragma unroll
        for (int h = 0; h < 2; ++h) {
            const int grow = m0 + wm * 64 + mt * 16 + g + h * 8;
            OutT* op = Oe + (size_t)grow * ldN + n0 + wn * 64 + cpair;
#pragma unroll
            for (int nt = 0; nt < 8; ++nt) {
                float x0 = acc[mt][nt][h * 2]     + bv[nt].x;
                float x1 = acc[mt][nt][h * 2 + 1] + bv[nt].y;
                if (GELU) {
                    __half2 hv = __floats2half2_rn(gelu_tanh(x0), gelu_tanh(x1));
                    *reinterpret_cast<__half2*>((__half*)op + nt * 8) = hv;
                } else {
                    *reinterpret_cast<float2*>((float*)op + nt * 8) =
                        make_float2(x0, x1);
                }
            }
        }
    }
}

// ---------------------------------------------------------------------------
// kernel_launch
// ---------------------------------------------------------------------------
extern "C" void kernel_launch(void* const* d_in, const int* in_sizes, int n_in,
                              void* d_out, int out_size) {
    (void)in_sizes; (void)n_in; (void)out_size;
    const float* inputs = (const float*)d_in[0];
    const float* w1     = (const float*)d_in[1];
    const float* b1     = (const float*)d_in[2];
    const float* w2     = (const float*)d_in[3];
    const float* b2     = (const float*)d_in[4];
    float* out = (float*)d_out;

    void *hp, *xp, *w1p, *w2p;
    cudaGetSymbolAddress(&hp,  g_H);
    cudaGetSymbolAddress(&xp,  g_Xh);
    cudaGetSymbolAddress(&w1p, g_W1h);
    cudaGetSymbolAddress(&w2p, g_W2h);
    __half* H   = (__half*)hp;
    __half* Xh  = (__half*)xp;
    __half* W1h = (__half*)w1p;
    __half* W2h = (__half*)w2p;

    const size_t nX = (size_t)EXP_E * EXP_C * EXP_D / 4;
    to_half_pass<<<2048, 256>>>((const float4*)inputs, (uint2*)Xh, nX);

    dim3 t1(EXP_F / 256, EXP_D / 64, EXP_E);   // W1: K=D, N=F
    transpose_pack64_h<<<t1, 256>>>(w1, W1h, EXP_D, EXP_F);
    dim3 t2(EXP_D / 256, EXP_F / 64, EXP_E);   // W2: K=F, N=D
    transpose_pack64_h<<<t2, 256>>>(w2, W2h, EXP_F, EXP_D);

    cudaFuncSetAttribute((const void*)moe_gemm_f16<true, __half>,
                         cudaFuncAttributeMaxDynamicSharedMemorySize, SMEM_BYTES);
    cudaFuncSetAttribute((const void*)moe_gemm_f16<false, float>,
                         cudaFuncAttributeMaxDynamicSharedMemorySize, SMEM_BYTES);

    dim3 g1(EXP_C / BM, EXP_F / BN, EXP_E);    // (16, 64, 8)
    moe_gemm_f16<true, __half><<<g1, 128, SMEM_BYTES>>>(Xh, W1h, b1, H, EXP_D, EXP_F);

    dim3 g2(EXP_C / BM, EXP_D / BN, EXP_E);    // (16, 16, 8)
    moe_gemm_f16<false, float><<<g2, 128, SMEM_BYTES>>>(H, W2h, b2, out, EXP_F, EXP_D);
}

// round 14
// speedup vs baseline: 1.1684x; 1.0009x over previous
#include <cuda_runtime.h>
#include <cuda_fp16.h>
#include <cstdint>
#include <math.h>

// ---------------------------------------------------------------------------
// 8-expert FFN, fp32: per expert [2048x2048]@[2048x8192] -> GELU -> @[8192x2048]
// compute_103 portable path. R14 = R13 (fp16 mma.m16n8k16, BK=64, 3 stages,
// 2 CTAs/SM, cross-tile pipelined mainloop) with the boundary race FIXED:
// CP_ASYNC_WAIT(1) (not 2) before ldmatrix of tile t+1 — pending groups at
// the boundary are exactly {t+1, t+2}, so WAIT(2) was a no-op and the kk0
// prefetch could read SMEM before tile t+1's cp.async landed.
// ---------------------------------------------------------------------------
#define EXP_E 8
#define EXP_C 2048
#define EXP_D 2048
#define EXP_F 8192

__device__ __align__(256) __half g_H  [(size_t)EXP_E * EXP_C * EXP_F];  // gelu(X@W1+b1)
__device__ __align__(256) __half g_Xh [(size_t)EXP_E * EXP_C * EXP_D];  // half X
__device__ __align__(256) __half g_W1h[(size_t)EXP_E * EXP_D * EXP_F];  // [E][D/64][F][64]
__device__ __align__(256) __half g_W2h[(size_t)EXP_E * EXP_F * EXP_D];  // [E][F/64][D][64]

#define BM 128
#define BN 128
#define BK 64
#define STAGES 3
#define ROW_BYTES 128                       // 64 halves per k-row
#define A_BYTES (BM * ROW_BYTES)            // 16384
#define B_BYTES (BN * ROW_BYTES)            // 16384
#define STAGE_BYTES (A_BYTES + B_BYTES)     // 32768
#define SMEM_BYTES (STAGES * STAGE_BYTES)   // 98304/CTA; 2 CTAs = 192KB/SM

// ---------------------------------------------------------------------------
// Helpers
// ---------------------------------------------------------------------------
__device__ __forceinline__ uint32_t smem_u32(const void* p) {
    uint32_t a;
    asm("{ .reg .u64 t; cvta.to.shared.u64 t, %1; cvt.u32.u64 %0, t; }"
        : "=r"(a) : "l"(p));
    return a;
}

#define CP_ASYNC_CG(dst_u32, src_ptr) \
    asm volatile("cp.async.cg.shared.global [%0], [%1], 16;" \
                 :: "r"(dst_u32), "l"(src_ptr) : "memory")
#define CP_ASYNC_COMMIT() asm volatile("cp.async.commit_group;" ::: "memory")
#define CP_ASYNC_WAIT(n)  asm volatile("cp.async.wait_group %0;" :: "n"(n) : "memory")

#define LDSM_X4(r, addr) \
    asm volatile("ldmatrix.sync.aligned.m8n8.x4.shared.b16 {%0,%1,%2,%3}, [%4];" \
                 : "=r"((r)[0]), "=r"((r)[1]), "=r"((r)[2]), "=r"((r)[3]) \
                 : "r"(addr))

// fp16 MMA, fp32 accumulate
__device__ __forceinline__ void mma_f16(float* d, const uint32_t* a,
                                        uint32_t b0, uint32_t b1) {
    asm volatile(
        "mma.sync.aligned.m16n8k16.row.col.f32.f16.f16.f32 "
        "{%0,%1,%2,%3}, {%4,%5,%6,%7}, {%8,%9}, {%0,%1,%2,%3};"
        : "+f"(d[0]), "+f"(d[1]), "+f"(d[2]), "+f"(d[3])
        : "r"(a[0]), "r"(a[1]), "r"(a[2]), "r"(a[3]), "r"(b0), "r"(b1));
}

__device__ __forceinline__ float gelu_tanh(float x) {
    float u = 0.7978845608028654f * fmaf(0.044715f * x, x * x, x);
    return 0.5f * x * (1.0f + tanhf(u));
}

// Convert X: fp32 -> fp16 (RNE).
__global__ void __launch_bounds__(256)
to_half_pass(const float4* __restrict__ in, uint2* __restrict__ out, size_t n4) {
    size_t i = (size_t)blockIdx.x * blockDim.x + threadIdx.x;
    size_t stride = (size_t)gridDim.x * blockDim.x;
    for (; i < n4; i += stride) {
        float4 v = in[i];
        __half2 h0 = __floats2half2_rn(v.x, v.y);
        __half2 h1 = __floats2half2_rn(v.z, v.w);
        uint2 u;
        u.x = *reinterpret_cast<uint32_t*>(&h0);
        u.y = *reinterpret_cast<uint32_t*>(&h1);
        out[i] = u;
    }
}

// Transpose-pack weights to half, 64-wide: W[e][k][n] -> Wt[e][k/64][n][64].
__global__ void __launch_bounds__(256)
transpose_pack64_h(const float* __restrict__ W, __half* __restrict__ Wt,
                   int K, int N) {
    const int n  = blockIdx.x * 256 + threadIdx.x;
    const int kt = blockIdx.y;
    const int e  = blockIdx.z;
    const float* src = W + ((size_t)e * K + (size_t)kt * 64) * N + n;
    __half* dst = Wt + (((size_t)e * (K / 64) + kt) * N + n) * 64;
#pragma unroll
    for (int j = 0; j < 64; j += 8) {
        uint4 u;
        __half2 h;
        h = __floats2half2_rn(src[(size_t)(j+0)*N], src[(size_t)(j+1)*N]);
        u.x = *reinterpret_cast<uint32_t*>(&h);
        h = __floats2half2_rn(src[(size_t)(j+2)*N], src[(size_t)(j+3)*N]);
        u.y = *reinterpret_cast<uint32_t*>(&h);
        h = __floats2half2_rn(src[(size_t)(j+4)*N], src[(size_t)(j+5)*N]);
        u.z = *reinterpret_cast<uint32_t*>(&h);
        h = __floats2half2_rn(src[(size_t)(j+6)*N], src[(size_t)(j+7)*N]);
        u.w = *reinterpret_cast<uint32_t*>(&h);
        *reinterpret_cast<uint4*>(dst + j) = u;
    }
}

// ---------------------------------------------------------------------------
// Batched GEMM: Out[e][m][n] = epi( sum_k A[e][m][k]*B[e][k][n] + bias[e][n] )
//   A:  [E][2048][K] row-major half
//   Bt: [E][K/64][ldN][64] K-major packed half
//   CTA 128x128x64, 128 threads (warp grid 2x2 of 64x64), 2 CTAs/SM.
// ---------------------------------------------------------------------------
template <bool GELU, typename OutT>
__global__ void __launch_bounds__(128, 2)
moe_gemm_f16(const __half* __restrict__ A, const __half* __restrict__ Bt,
             const float* __restrict__ bias, OutT* __restrict__ Out,
             int K, int ldN)
{
    extern __shared__ char smem[];
    const int tid  = threadIdx.x;
    const int warp = tid >> 5;
    const int lane = tid & 31;
    const int e  = blockIdx.z;
    const int m0 = blockIdx.x * BM;
    const int n0 = blockIdx.y * BN;
    const int KT = K / BK;

    const __half* Ae  = A  + (size_t)e * EXP_C * K;
    const __half* Bte = Bt + (size_t)e * (K / 64) * ldN * 64 + (size_t)n0 * 64;
    const float*  be  = bias + (size_t)e * ldN;
    OutT*         Oe  = Out  + (size_t)e * EXP_C * ldN;

    const uint32_t sbase = smem_u32(smem);

    const int wm = warp >> 1;    // warp grid 2(M) x 2(N), warp tile 64x64
    const int wn = warp & 1;

    // ---- cp.async geometry ----
    const int crow   = tid >> 3;              // 0..15
    const int cchunk = tid & 7;               // 8 x 16B per 128B row
    const int cswz   = crow & 7;
    const uint32_t a_dst0 = (uint32_t)(crow * ROW_BYTES + ((cchunk ^ cswz) * 16));

    const __half* a_run = Ae  + (size_t)(m0 + crow) * K + cchunk * 8;
    const __half* b_run = Bte + (size_t)crow * 64 + cchunk * 8;

    // ---- ldmatrix geometry (kk-step address = base ^ (kk*32)) ----
    const int alrow = (lane & 7) + ((lane >> 3) & 1) * 8;
    const int ahi   = lane >> 4;
    const int blrow = (lane & 7) + ((lane >> 4) & 1) * 8;
    const int bhi   = (lane >> 3) & 1;
    uint32_t afrag[4], bfrag[4];
#pragma unroll
    for (int i = 0; i < 4; ++i) {
        int ra = wm * 64 + i * 16 + alrow;
        afrag[i] = (uint32_t)(ra * ROW_BYTES + ((ahi ^ (ra & 7)) * 16));
        int rb = wn * 64 + i * 16 + blrow;
        bfrag[i] = (uint32_t)(A_BYTES + rb * ROW_BYTES + ((bhi ^ (rb & 7)) * 16));
    }

    float acc[4][8][4];
#pragma unroll
    for (int mt = 0; mt < 4; ++mt)
#pragma unroll
        for (int nt = 0; nt < 8; ++nt)
#pragma unroll
            for (int j = 0; j < 4; ++j) acc[mt][nt][j] = 0.0f;

    auto issue_tile = [&](int stg) {
        const uint32_t st = sbase + (uint32_t)stg * STAGE_BYTES;
#pragma unroll
        for (int rep = 0; rep < 8; ++rep)
            CP_ASYNC_CG(st + a_dst0 + rep * 16u * ROW_BYTES,
                        a_run + (size_t)rep * 16 * K);
#pragma unroll
        for (int rep = 0; rep < 8; ++rep)
            CP_ASYNC_CG(st + A_BYTES + a_dst0 + rep * 16u * ROW_BYTES,
                        b_run + rep * 16 * 64);
        a_run += BK;
        b_run += (size_t)ldN * 64;
    };

    // prologue: fill ALL 3 stages (KT = 32 or 128 >= 3 always)
#pragma unroll
    for (int t = 0; t < STAGES; ++t) {
        issue_tile(t);
        CP_ASYNC_COMMIT();
    }
    CP_ASYNC_WAIT(2);          // pending {0,1,2} -> tile 0 resident
    __syncthreads();

    // preload tile 0 / kk 0 fragments
    uint32_t af[2][4][4], bf[2][4][4];
#pragma unroll
    for (int i = 0; i < 4; ++i) LDSM_X4(af[0][i], sbase + afrag[i]);
#pragma unroll
    for (int i = 0; i < 4; ++i) LDSM_X4(bf[0][i], sbase + bfrag[i]);

    int s_cur = 0;
    for (int t = 0; t < KT; ++t) {
        const uint32_t sA = sbase + (uint32_t)s_cur * STAGE_BYTES;
        const int s_nxt = (s_cur + 1 == STAGES) ? 0 : s_cur + 1;
        const uint32_t sN = sbase + (uint32_t)s_nxt * STAGE_BYTES;

#pragma unroll
        for (int kk = 0; kk < 4; ++kk) {
            const int cur = kk & 1, nxt = cur ^ 1;
            if (kk < 3) {
                // prefetch fragments for kk+1 (same stage)
                const uint32_t x = (uint32_t)(kk + 1) * 32u;
#pragma unroll
                for (int i = 0; i < 4; ++i) LDSM_X4(af[nxt][i], sA + (afrag[i] ^ x));
#pragma unroll
                for (int i = 0; i < 4; ++i) LDSM_X4(bf[nxt][i], sA + (bfrag[i] ^ x));
            } else {
                // cross-tile boundary BEFORE kk3's MMA burst.
                // Pending groups here are exactly {t+1, t+2}; WAIT(1) is the
                // weakest wait that guarantees tile t+1's data has landed.
                CP_ASYNC_WAIT(1);
                __syncthreads();
                if (t + 1 < KT) {
#pragma unroll
                    for (int i = 0; i < 4; ++i) LDSM_X4(af[nxt][i], sN + afrag[i]);
#pragma unroll
                    for (int i = 0; i < 4; ++i) LDSM_X4(bf[nxt][i], sN + bfrag[i]);
                }
                if (t + STAGES < KT) issue_tile(s_cur);   // tile t+3 -> freed stage
                CP_ASYNC_COMMIT();                        // uniform group count
            }
#pragma unroll
            for (int mt = 0; mt < 4; ++mt)
#pragma unroll
                for (int nt = 0; nt < 8; ++nt)
                    mma_f16(acc[mt][nt], af[cur][mt],
                            bf[cur][nt >> 1][(nt & 1) * 2],
                            bf[cur][nt >> 1][(nt & 1) * 2 + 1]);
        }
        s_cur = s_nxt;
    }

    // ---- epilogue: direct reg -> gmem, fused bias (+GELU) ----
    const int g     = lane >> 2;
    const int cpair = (lane & 3) * 2;
    float2 bv[8];
#pragma unroll
    for (int nt = 0; nt < 8; ++nt)
        bv[nt] = *reinterpret_cast<const float2*>(be + n0 + wn * 64 + nt * 8 + cpair);

#pragma unroll
    for (int mt = 0; mt < 4; ++mt) {
#pragma unroll
        for (int h = 0; h < 2; ++h) {
            const int grow = m0 + wm * 64 + mt * 16 + g + h * 8;
            OutT* op = Oe + (size_t)grow * ldN + n0 + wn * 64 + cpair;
#pragma unroll
            for (int nt = 0; nt < 8; ++nt) {
                float x0 = acc[mt][nt][h * 2]     + bv[nt].x;
                float x1 = acc[mt][nt][h * 2 + 1] + bv[nt].y;
                if (GELU) {
                    __half2 hv = __floats2half2_rn(gelu_tanh(x0), gelu_tanh(x1));
                    *reinterpret_cast<__half2*>((__half*)op + nt * 8) = hv;
                } else {
                    *reinterpret_cast<float2*>((float*)op + nt * 8) =
                        make_float2(x0, x1);
                }
            }
        }
    }
}

// ---------------------------------------------------------------------------
// kernel_launch
// ---------------------------------------------------------------------------
extern "C" void kernel_launch(void* const* d_in, const int* in_sizes, int n_in,
                              void* d_out, int out_size) {
    (void)in_sizes; (void)n_in; (void)out_size;
    const float* inputs = (const float*)d_in[0];
    const float* w1     = (const float*)d_in[1];
    const float* b1     = (const float*)d_in[2];
    const float* w2     = (const float*)d_in[3];
    const float* b2     = (const float*)d_in[4];
    float* out = (float*)d_out;

    void *hp, *xp, *w1p, *w2p;
    cudaGetSymbolAddress(&hp,  g_H);
    cudaGetSymbolAddress(&xp,  g_Xh);
    cudaGetSymbolAddress(&w1p, g_W1h);
    cudaGetSymbolAddress(&w2p, g_W2h);
    __half* H   = (__half*)hp;
    __half* Xh  = (__half*)xp;
    __half* W1h = (__half*)w1p;
    __half* W2h = (__half*)w2p;

    const size_t nX = (size_t)EXP_E * EXP_C * EXP_D / 4;
    to_half_pass<<<2048, 256>>>((const float4*)inputs, (uint2*)Xh, nX);

    dim3 t1(EXP_F / 256, EXP_D / 64, EXP_E);   // W1: K=D, N=F
    transpose_pack64_h<<<t1, 256>>>(w1, W1h, EXP_D, EXP_F);
    dim3 t2(EXP_D / 256, EXP_F / 64, EXP_E);   // W2: K=F, N=D
    transpose_pack64_h<<<t2, 256>>>(w2, W2h, EXP_F, EXP_D);

    cudaFuncSetAttribute((const void*)moe_gemm_f16<true, __half>,
                         cudaFuncAttributeMaxDynamicSharedMemorySize, SMEM_BYTES);
    cudaFuncSetAttribute((const void*)moe_gemm_f16<false, float>,
                         cudaFuncAttributeMaxDynamicSharedMemorySize, SMEM_BYTES);

    dim3 g1(EXP_C / BM, EXP_F / BN, EXP_E);    // (16, 64, 8)
    moe_gemm_f16<true, __half><<<g1, 128, SMEM_BYTES>>>(Xh, W1h, b1, H, EXP_D, EXP_F);

    dim3 g2(EXP_C / BM, EXP_D / BN, EXP_E);    // (16, 16, 8)
    moe_gemm_f16<false, float><<<g2, 128, SMEM_BYTES>>>(H, W2h, b2, out, EXP_F, EXP_D);
}

// round 15
// speedup vs baseline: 1.1915x; 1.0198x over previous
#include <cuda_runtime.h>
#include <cuda_fp16.h>
#include <cstdint>
#include <math.h>

// ---------------------------------------------------------------------------
// 8-expert FFN, fp32: per expert [2048x2048]@[2048x8192] -> GELU -> @[8192x2048]
// compute_103 portable path. R15 = R14 (fp16 mma.m16n8k16, BK=64, 3 stages,
// 2 CTAs/SM, race-free cross-tile pipelined mainloop) + hardware
// tanh.approx.f32 in the GELU epilogue (sm_75+ MUFU, err ~2^-11) replacing
// the ~20-instruction precise tanhf() that dominated GEMM1's epilogue.
// ---------------------------------------------------------------------------
#define EXP_E 8
#define EXP_C 2048
#define EXP_D 2048
#define EXP_F 8192

__device__ __align__(256) __half g_H  [(size_t)EXP_E * EXP_C * EXP_F];  // gelu(X@W1+b1)
__device__ __align__(256) __half g_Xh [(size_t)EXP_E * EXP_C * EXP_D];  // half X
__device__ __align__(256) __half g_W1h[(size_t)EXP_E * EXP_D * EXP_F];  // [E][D/64][F][64]
__device__ __align__(256) __half g_W2h[(size_t)EXP_E * EXP_F * EXP_D];  // [E][F/64][D][64]

#define BM 128
#define BN 128
#define BK 64
#define STAGES 3
#define ROW_BYTES 128                       // 64 halves per k-row
#define A_BYTES (BM * ROW_BYTES)            // 16384
#define B_BYTES (BN * ROW_BYTES)            // 16384
#define STAGE_BYTES (A_BYTES + B_BYTES)     // 32768
#define SMEM_BYTES (STAGES * STAGE_BYTES)   // 98304/CTA; 2 CTAs = 192KB/SM

// ---------------------------------------------------------------------------
// Helpers
// ---------------------------------------------------------------------------
__device__ __forceinline__ uint32_t smem_u32(const void* p) {
    uint32_t a;
    asm("{ .reg .u64 t; cvta.to.shared.u64 t, %1; cvt.u32.u64 %0, t; }"
        : "=r"(a) : "l"(p));
    return a;
}

#define CP_ASYNC_CG(dst_u32, src_ptr) \
    asm volatile("cp.async.cg.shared.global [%0], [%1], 16;" \
                 :: "r"(dst_u32), "l"(src_ptr) : "memory")
#define CP_ASYNC_COMMIT() asm volatile("cp.async.commit_group;" ::: "memory")
#define CP_ASYNC_WAIT(n)  asm volatile("cp.async.wait_group %0;" :: "n"(n) : "memory")

#define LDSM_X4(r, addr) \
    asm volatile("ldmatrix.sync.aligned.m8n8.x4.shared.b16 {%0,%1,%2,%3}, [%4];" \
                 : "=r"((r)[0]), "=r"((r)[1]), "=r"((r)[2]), "=r"((r)[3]) \
                 : "r"(addr))

// fp16 MMA, fp32 accumulate
__device__ __forceinline__ void mma_f16(float* d, const uint32_t* a,
                                        uint32_t b0, uint32_t b1) {
    asm volatile(
        "mma.sync.aligned.m16n8k16.row.col.f32.f16.f16.f32 "
        "{%0,%1,%2,%3}, {%4,%5,%6,%7}, {%8,%9}, {%0,%1,%2,%3};"
        : "+f"(d[0]), "+f"(d[1]), "+f"(d[2]), "+f"(d[3])
        : "r"(a[0]), "r"(a[1]), "r"(a[2]), "r"(a[3]), "r"(b0), "r"(b1));
}

// HW tanh (sm_75+ MUFU): single instruction, max err ~2^-11.
__device__ __forceinline__ float tanh_hw(float x) {
    float y;
    asm("tanh.approx.f32 %0, %1;" : "=f"(y) : "f"(x));
    return y;
}

__device__ __forceinline__ float gelu_tanh(float x) {
    float u = 0.7978845608028654f * fmaf(0.044715f * x, x * x, x);
    return 0.5f * x * (1.0f + tanh_hw(u));
}

// Convert X: fp32 -> fp16 (RNE).
__global__ void __launch_bounds__(256)
to_half_pass(const float4* __restrict__ in, uint2* __restrict__ out, size_t n4) {
    size_t i = (size_t)blockIdx.x * blockDim.x + threadIdx.x;
    size_t stride = (size_t)gridDim.x * blockDim.x;
    for (; i < n4; i += stride) {
        float4 v = in[i];
        __half2 h0 = __floats2half2_rn(v.x, v.y);
        __half2 h1 = __floats2half2_rn(v.z, v.w);
        uint2 u;
        u.x = *reinterpret_cast<uint32_t*>(&h0);
        u.y = *reinterpret_cast<uint32_t*>(&h1);
        out[i] = u;
    }
}

// Transpose-pack weights to half, 64-wide: W[e][k][n] -> Wt[e][k/64][n][64].
__global__ void __launch_bounds__(256)
transpose_pack64_h(const float* __restrict__ W, __half* __restrict__ Wt,
                   int K, int N) {
    const int n  = blockIdx.x * 256 + threadIdx.x;
    const int kt = blockIdx.y;
    const int e  = blockIdx.z;
    const float* src = W + ((size_t)e * K + (size_t)kt * 64) * N + n;
    __half* dst = Wt + (((size_t)e * (K / 64) + kt) * N + n) * 64;
#pragma unroll
    for (int j = 0; j < 64; j += 8) {
        uint4 u;
        __half2 h;
        h = __floats2half2_rn(src[(size_t)(j+0)*N], src[(size_t)(j+1)*N]);
        u.x = *reinterpret_cast<uint32_t*>(&h);
        h = __floats2half2_rn(src[(size_t)(j+2)*N], src[(size_t)(j+3)*N]);
        u.y = *reinterpret_cast<uint32_t*>(&h);
        h = __floats2half2_rn(src[(size_t)(j+4)*N], src[(size_t)(j+5)*N]);
        u.z = *reinterpret_cast<uint32_t*>(&h);
        h = __floats2half2_rn(src[(size_t)(j+6)*N], src[(size_t)(j+7)*N]);
        u.w = *reinterpret_cast<uint32_t*>(&h);
        *reinterpret_cast<uint4*>(dst + j) = u;
    }
}

// ---------------------------------------------------------------------------
// Batched GEMM: Out[e][m][n] = epi( sum_k A[e][m][k]*B[e][k][n] + bias[e][n] )
//   A:  [E][2048][K] row-major half
//   Bt: [E][K/64][ldN][64] K-major packed half
//   CTA 128x128x64, 128 threads (warp grid 2x2 of 64x64), 2 CTAs/SM.
// ---------------------------------------------------------------------------
template <bool GELU, typename OutT>
__global__ void __launch_bounds__(128, 2)
moe_gemm_f16(const __half* __restrict__ A, const __half* __restrict__ Bt,
             const float* __restrict__ bias, OutT* __restrict__ Out,
             int K, int ldN)
{
    extern __shared__ char smem[];
    const int tid  = threadIdx.x;
    const int warp = tid >> 5;
    const int lane = tid & 31;
    const int e  = blockIdx.z;
    const int m0 = blockIdx.x * BM;
    const int n0 = blockIdx.y * BN;
    const int KT = K / BK;

    const __half* Ae  = A  + (size_t)e * EXP_C * K;
    const __half* Bte = Bt + (size_t)e * (K / 64) * ldN * 64 + (size_t)n0 * 64;
    const float*  be  = bias + (size_t)e * ldN;
    OutT*         Oe  = Out  + (size_t)e * EXP_C * ldN;

    const uint32_t sbase = smem_u32(smem);

    const int wm = warp >> 1;    // warp grid 2(M) x 2(N), warp tile 64x64
    const int wn = warp & 1;

    // ---- cp.async geometry ----
    const int crow   = tid >> 3;              // 0..15
    const int cchunk = tid & 7;               // 8 x 16B per 128B row
    const int cswz   = crow & 7;
    const uint32_t a_dst0 = (uint32_t)(crow * ROW_BYTES + ((cchunk ^ cswz) * 16));

    const __half* a_run = Ae  + (size_t)(m0 + crow) * K + cchunk * 8;
    const __half* b_run = Bte + (size_t)crow * 64 + cchunk * 8;

    // ---- ldmatrix geometry (kk-step address = base ^ (kk*32)) ----
    const int alrow = (lane & 7) + ((lane >> 3) & 1) * 8;
    const int ahi   = lane >> 4;
    const int blrow = (lane & 7) + ((lane >> 4) & 1) * 8;
    const int bhi   = (lane >> 3) & 1;
    uint32_t afrag[4], bfrag[4];
#pragma unroll
    for (int i = 0; i < 4; ++i) {
        int ra = wm * 64 + i * 16 + alrow;
        afrag[i] = (uint32_t)(ra * ROW_BYTES + ((ahi ^ (ra & 7)) * 16));
        int rb = wn * 64 + i * 16 + blrow;
        bfrag[i] = (uint32_t)(A_BYTES + rb * ROW_BYTES + ((bhi ^ (rb & 7)) * 16));
    }

    float acc[4][8][4];
#pragma unroll
    for (int mt = 0; mt < 4; ++mt)
#pragma unroll
        for (int nt = 0; nt < 8; ++nt)
#pragma unroll
            for (int j = 0; j < 4; ++j) acc[mt][nt][j] = 0.0f;

    auto issue_tile = [&](int stg) {
        const uint32_t st = sbase + (uint32_t)stg * STAGE_BYTES;
#pragma unroll
        for (int rep = 0; rep < 8; ++rep)
            CP_ASYNC_CG(st + a_dst0 + rep * 16u * ROW_BYTES,
                        a_run + (size_t)rep * 16 * K);
#pragma unroll
        for (int rep = 0; rep < 8; ++rep)
            CP_ASYNC_CG(st + A_BYTES + a_dst0 + rep * 16u * ROW_BYTES,
                        b_run + rep * 16 * 64);
        a_run += BK;
        b_run += (size_t)ldN * 64;
    };

    // prologue: fill ALL 3 stages (KT >= 3 always here)
#pragma unroll
    for (int t = 0; t < STAGES; ++t) {
        issue_tile(t);
        CP_ASYNC_COMMIT();
    }
    CP_ASYNC_WAIT(2);          // pending {0,1,2} -> tile 0 resident
    __syncthreads();

    // preload tile 0 / kk 0 fragments
    uint32_t af[2][4][4], bf[2][4][4];
#pragma unroll
    for (int i = 0; i < 4; ++i) LDSM_X4(af[0][i], sbase + afrag[i]);
#pragma unroll
    for (int i = 0; i < 4; ++i) LDSM_X4(bf[0][i], sbase + bfrag[i]);

    int s_cur = 0;
    for (int t = 0; t < KT; ++t) {
        const uint32_t sA = sbase + (uint32_t)s_cur * STAGE_BYTES;
        const int s_nxt = (s_cur + 1 == STAGES) ? 0 : s_cur + 1;
        const uint32_t sN = sbase + (uint32_t)s_nxt * STAGE_BYTES;

#pragma unroll
        for (int kk = 0; kk < 4; ++kk) {
            const int cur = kk & 1, nxt = cur ^ 1;
            if (kk < 3) {
                // prefetch fragments for kk+1 (same stage)
                const uint32_t x = (uint32_t)(kk + 1) * 32u;
#pragma unroll
                for (int i = 0; i < 4; ++i) LDSM_X4(af[nxt][i], sA + (afrag[i] ^ x));
#pragma unroll
                for (int i = 0; i < 4; ++i) LDSM_X4(bf[nxt][i], sA + (bfrag[i] ^ x));
            } else {
                // cross-tile boundary BEFORE kk3's MMA burst.
                // Pending groups here are exactly {t+1, t+2}; WAIT(1) is the
                // weakest wait that guarantees tile t+1's data has landed.
                CP_ASYNC_WAIT(1);
                __syncthreads();
                if (t + 1 < KT) {
#pragma unroll
                    for (int i = 0; i < 4; ++i) LDSM_X4(af[nxt][i], sN + afrag[i]);
#pragma unroll
                    for (int i = 0; i < 4; ++i) LDSM_X4(bf[nxt][i], sN + bfrag[i]);
                }
                if (t + STAGES < KT) issue_tile(s_cur);   // tile t+3 -> freed stage
                CP_ASYNC_COMMIT();                        // uniform group count
            }
#pragma unroll
            for (int mt = 0; mt < 4; ++mt)
#pragma unroll
                for (int nt = 0; nt < 8; ++nt)
                    mma_f16(acc[mt][nt], af[cur][mt],
                            bf[cur][nt >> 1][(nt & 1) * 2],
                            bf[cur][nt >> 1][(nt & 1) * 2 + 1]);
        }
        s_cur = s_nxt;
    }

    // ---- epilogue: direct reg -> gmem, fused bias (+GELU via HW tanh) ----
    const int g     = lane >> 2;
    const int cpair = (lane & 3) * 2;
    float2 bv[8];
#pragma unroll
    for (int nt = 0; nt < 8; ++nt)
        bv[nt] = *reinterpret_cast<const float2*>(be + n0 + wn * 64 + nt * 8 + cpair);

#pragma unroll
    for (int mt = 0; mt < 4; ++mt) {
#pragma unroll
        for (int h = 0; h < 2; ++h) {
            const int grow = m0 + wm * 64 + mt * 16 + g + h * 8;
            OutT* op = Oe + (size_t)grow * ldN + n0 + wn * 64 + cpair;
#pragma unroll
            for (int nt = 0; nt < 8; ++nt) {
                float x0 = acc[mt][nt][h * 2]     + bv[nt].x;
                float x1 = acc[mt][nt][h * 2 + 1] + bv[nt].y;
                if (GELU) {
                    __half2 hv = __floats2half2_rn(gelu_tanh(x0), gelu_tanh(x1));
                    *reinterpret_cast<__half2*>((__half*)op + nt * 8) = hv;
                } else {
                    *reinterpret_cast<float2*>((float*)op + nt * 8) =
                        make_float2(x0, x1);
                }
            }
        }
    }
}

// ---------------------------------------------------------------------------
// kernel_launch
// ---------------------------------------------------------------------------
extern "C" void kernel_launch(void* const* d_in, const int* in_sizes, int n_in,
                              void* d_out, int out_size) {
    (void)in_sizes; (void)n_in; (void)out_size;
    const float* inputs = (const float*)d_in[0];
    const float* w1     = (const float*)d_in[1];
    const float* b1     = (const float*)d_in[2];
    const float* w2     = (const float*)d_in[3];
    const float* b2     = (const float*)d_in[4];
    float* out = (float*)d_out;

    void *hp, *xp, *w1p, *w2p;
    cudaGetSymbolAddress(&hp,  g_H);
    cudaGetSymbolAddress(&xp,  g_Xh);
    cudaGetSymbolAddress(&w1p, g_W1h);
    cudaGetSymbolAddress(&w2p, g_W2h);
    __half* H   = (__half*)hp;
    __half* Xh  = (__half*)xp;
    __half* W1h = (__half*)w1p;
    __half* W2h = (__half*)w2p;

    const size_t nX = (size_t)EXP_E * EXP_C * EXP_D / 4;
    to_half_pass<<<2048, 256>>>((const float4*)inputs, (uint2*)Xh, nX);

    dim3 t1(EXP_F / 256, EXP_D / 64, EXP_E);   // W1: K=D, N=F
    transpose_pack64_h<<<t1, 256>>>(w1, W1h, EXP_D, EXP_F);
    dim3 t2(EXP_D / 256, EXP_F / 64, EXP_E);   // W2: K=F, N=D
    transpose_pack64_h<<<t2, 256>>>(w2, W2h, EXP_F, EXP_D);

    cudaFuncSetAttribute((const void*)moe_gemm_f16<true, __half>,
                         cudaFuncAttributeMaxDynamicSharedMemorySize, SMEM_BYTES);
    cudaFuncSetAttribute((const void*)moe_gemm_f16<false, float>,
                         cudaFuncAttributeMaxDynamicSharedMemorySize, SMEM_BYTES);

    dim3 g1(EXP_C / BM, EXP_F / BN, EXP_E);    // (16, 64, 8)
    moe_gemm_f16<true, __half><<<g1, 128, SMEM_BYTES>>>(Xh, W1h, b1, H, EXP_D, EXP_F);

    dim3 g2(EXP_C / BM, EXP_D / BN, EXP_E);    // (16, 16, 8)
    moe_gemm_f16<false, float><<<g2, 128, SMEM_BYTES>>>(H, W2h, b2, out, EXP_F, EXP_D);
}